// round 1
// baseline (speedup 1.0000x reference)
#include <cuda_runtime.h>
#include <cuda_bf16.h>
#include <math.h>

// Problem constants
#define B_    2
#define L_    2048
#define D_    2048
#define H_    16
#define KVH_  4
#define DK_   128
#define DKV_  512            // KVH_ * DK_
#define M_    (B_ * L_)      // 4096 rows
#define CAPV  50.0f

// ---------------- scratch (static device globals; no allocation) ----------------
static __device__ float g_Q[(size_t)M_ * D_];    // 33.5 MB
static __device__ float g_K[(size_t)M_ * DKV_];  //  8.4 MB
static __device__ float g_V[(size_t)M_ * DKV_];  //  8.4 MB
static __device__ float g_O[(size_t)M_ * D_];    // 33.5 MB
static __device__ float g_cos[L_ * 64];
static __device__ float g_sin[L_ * 64];

// ---------------- RoPE table ----------------
__global__ void rope_table_kernel() {
    int idx = blockIdx.x * blockDim.x + threadIdx.x;
    if (idx >= L_ * 64) return;
    int pos = idx >> 6;
    int i   = idx & 63;
    float expnt = (float)(2 * i) / 128.0f;
    float invf  = powf(10000.0f, -expnt);
    float f     = (float)pos * invf;
    g_cos[idx] = cosf(f);
    g_sin[idx] = sinf(f);
}

// ---------------- RoPE apply + clip (in place) ----------------
__global__ void rope_apply_kernel(float* __restrict__ X, int heads, int rowstride) {
    int idx   = blockIdx.x * blockDim.x + threadIdx.x;
    int total = M_ * heads * 64;
    if (idx >= total) return;
    int i   = idx & 63;
    int t   = idx >> 6;
    int h   = t % heads;
    int row = t / heads;
    int pos = row & (L_ - 1);
    float c = g_cos[(pos << 6) + i];
    float s = g_sin[(pos << 6) + i];
    float* p = X + (size_t)row * rowstride + h * DK_ + i;
    float x1 = p[0], x2 = p[64];
    float o1 = x1 * c - x2 * s;
    float o2 = x1 * s + x2 * c;
    p[0]  = fminf(fmaxf(o1, -CAPV), CAPV);
    p[64] = fminf(fmaxf(o2, -CAPV), CAPV);
}

// ---------------- fp32 NT GEMM: C[M,N] = A[M,K] * B[N,K]^T ----------------
// BM=BN=128, BK=8, 256 threads, 8x8 accumulators per thread, register prefetch.
__global__ void __launch_bounds__(256) gemm_nt_kernel(
    const float* __restrict__ A, const float* __restrict__ Bw,
    float* __restrict__ C, int M, int N, int K)
{
    __shared__ float As[8][128];
    __shared__ float Bs[8][128];

    const int tid = threadIdx.x;
    const int tx  = tid & 15;
    const int ty  = tid >> 4;
    const int bm  = blockIdx.y << 7;
    const int bn  = blockIdx.x << 7;

    const int lrow = tid >> 1;           // 0..127
    const int lcol = (tid & 1) << 2;     // 0 or 4
    const float* Ap = A  + (size_t)(bm + lrow) * K + lcol;
    const float* Bp = Bw + (size_t)(bn + lrow) * K + lcol;

    float acc[8][8];
    #pragma unroll
    for (int i = 0; i < 8; i++)
        #pragma unroll
        for (int j = 0; j < 8; j++) acc[i][j] = 0.0f;

    float4 av = *(const float4*)(Ap);
    float4 bv = *(const float4*)(Bp);

    for (int k0 = 0; k0 < K; k0 += 8) {
        __syncthreads();
        As[lcol + 0][lrow] = av.x; As[lcol + 1][lrow] = av.y;
        As[lcol + 2][lrow] = av.z; As[lcol + 3][lrow] = av.w;
        Bs[lcol + 0][lrow] = bv.x; Bs[lcol + 1][lrow] = bv.y;
        Bs[lcol + 2][lrow] = bv.z; Bs[lcol + 3][lrow] = bv.w;
        __syncthreads();

        if (k0 + 8 < K) {               // prefetch next K-slab
            av = *(const float4*)(Ap + k0 + 8);
            bv = *(const float4*)(Bp + k0 + 8);
        }

        #pragma unroll
        for (int kk = 0; kk < 8; kk++) {
            float a[8], b[8];
            #pragma unroll
            for (int i = 0; i < 8; i++) a[i] = As[kk][(ty << 3) + i];
            #pragma unroll
            for (int j = 0; j < 8; j++) b[j] = Bs[kk][(tx << 3) + j];
            #pragma unroll
            for (int i = 0; i < 8; i++)
                #pragma unroll
                for (int j = 0; j < 8; j++)
                    acc[i][j] += a[i] * b[j];
        }
    }

    #pragma unroll
    for (int i = 0; i < 8; i++) {
        float* cp = C + (size_t)(bm + (ty << 3) + i) * N + bn + (tx << 3);
        float4 v0 = make_float4(acc[i][0], acc[i][1], acc[i][2], acc[i][3]);
        float4 v1 = make_float4(acc[i][4], acc[i][5], acc[i][6], acc[i][7]);
        *(float4*)(cp)     = v0;
        *(float4*)(cp + 4) = v1;
    }
}

// ---------------- flash attention (fp32, causal) ----------------
#define AP 133   // smem pitch for 64x128 tiles: 4*col-stride patterns conflict-free/2-way
#define PP 65    // smem pitch for 64x64 P tile
#define ATTN_SMEM_FLOATS (2 * 64 * AP + 64 * PP + 3 * 64)
#define ATTN_SMEM_BYTES  (ATTN_SMEM_FLOATS * 4)

__device__ __forceinline__ void load_tile_64x128(float* dst, const float* __restrict__ src,
                                                 int rs, int tid) {
    #pragma unroll
    for (int it = 0; it < 8; it++) {
        int lin = tid + (it << 8);        // 0..2047 float4s
        int r   = lin >> 5;
        int c   = (lin & 31) << 2;
        float4 v = *(const float4*)(src + (size_t)r * rs + c);
        float* d = dst + r * AP + c;
        d[0] = v.x; d[1] = v.y; d[2] = v.z; d[3] = v.w;
    }
}

__global__ void __launch_bounds__(256) attn_kernel() {
    extern __shared__ float smbuf[];
    float* Qs  = smbuf;
    float* KVs = smbuf + 64 * AP;
    float* Ps  = smbuf + 2 * 64 * AP;
    float* smM = Ps + 64 * PP;
    float* smL = smM + 64;
    float* smF = smL + 64;

    const int tid = threadIdx.x;
    const int tx  = tid & 15;
    const int ty  = tid >> 4;
    const int qb  = blockIdx.x;
    const int h   = blockIdx.y;
    const int b   = blockIdx.z;
    const int q0  = qb << 6;
    const int kvh = h >> 2;   // REP = 4

    const float* Qg = g_Q + (size_t)(b * L_ + q0) * D_ + h * DK_;
    const float* Kg = g_K + (size_t)(b * L_) * DKV_ + kvh * DK_;
    const float* Vg = g_V + (size_t)(b * L_) * DKV_ + kvh * DK_;

    load_tile_64x128(Qs, Qg, D_, tid);
    if (tid < 64) { smM[tid] = -1e30f; smL[tid] = 0.0f; }

    float o[4][8];
    #pragma unroll
    for (int i = 0; i < 4; i++)
        #pragma unroll
        for (int c = 0; c < 8; c++) o[i][c] = 0.0f;

    const float scale = 0.08838834764831845f;  // 1/sqrt(128)
    const int nkb = qb + 1;

    for (int kb = 0; kb < nkb; kb++) {
        const int k0 = kb << 6;
        __syncthreads();   // prev PV reads of KVs/Ps done; Q visible on iter 0
        load_tile_64x128(KVs, Kg + (size_t)k0 * DKV_, DKV_, tid);
        __syncthreads();

        // S = Q K^T  (thread: rows 4ty+i, cols tx+16j)
        float s[4][4];
        #pragma unroll
        for (int i = 0; i < 4; i++)
            #pragma unroll
            for (int j = 0; j < 4; j++) s[i][j] = 0.0f;

        #pragma unroll 4
        for (int d = 0; d < DK_; d++) {
            float qv[4], kv[4];
            #pragma unroll
            for (int i = 0; i < 4; i++) qv[i] = Qs[(4 * ty + i) * AP + d];
            #pragma unroll
            for (int j = 0; j < 4; j++) kv[j] = KVs[(tx + 16 * j) * AP + d];
            #pragma unroll
            for (int i = 0; i < 4; i++)
                #pragma unroll
                for (int j = 0; j < 4; j++)
                    s[i][j] += qv[i] * kv[j];
        }

        #pragma unroll
        for (int i = 0; i < 4; i++) {
            int r = 4 * ty + i;
            #pragma unroll
            for (int j = 0; j < 4; j++) {
                int c = tx + 16 * j;
                float val = s[i][j] * scale;
                if (k0 + c > q0 + r) val = -1e30f;   // causal mask
                Ps[r * PP + c] = val;
            }
        }
        __syncthreads();

        // online softmax, one thread per row
        if (tid < 64) {
            int r = tid;
            float m0 = smM[r];
            float mx = m0;
            #pragma unroll 4
            for (int c = 0; c < 64; c++) mx = fmaxf(mx, Ps[r * PP + c]);
            float fac = __expf(m0 - mx);
            float l = smL[r] * fac;
            #pragma unroll 4
            for (int c = 0; c < 64; c++) {
                float p = __expf(Ps[r * PP + c] - mx);
                Ps[r * PP + c] = p;
                l += p;
            }
            smM[r] = mx; smL[r] = l; smF[r] = fac;
        }
        __syncthreads();

        // rescale O; load V over the K buffer
        float f[4];
        #pragma unroll
        for (int i = 0; i < 4; i++) f[i] = smF[4 * ty + i];
        #pragma unroll
        for (int i = 0; i < 4; i++)
            #pragma unroll
            for (int c = 0; c < 8; c++) o[i][c] *= f[i];

        load_tile_64x128(KVs, Vg + (size_t)k0 * DKV_, DKV_, tid);
        __syncthreads();

        // O += P V   (thread: rows 4ty+i, cols tx+16c)
        #pragma unroll 2
        for (int kk = 0; kk < 64; kk++) {
            float p[4], v[8];
            #pragma unroll
            for (int i = 0; i < 4; i++) p[i] = Ps[(4 * ty + i) * PP + kk];
            #pragma unroll
            for (int c = 0; c < 8; c++) v[c] = KVs[kk * AP + tx + 16 * c];
            #pragma unroll
            for (int i = 0; i < 4; i++)
                #pragma unroll
                for (int c = 0; c < 8; c++)
                    o[i][c] += p[i] * v[c];
        }
    }

    // epilogue: normalize and write
    #pragma unroll
    for (int i = 0; i < 4; i++) {
        int r = 4 * ty + i;
        float inv = 1.0f / smL[r];
        float* op = g_O + (size_t)(b * L_ + q0 + r) * D_ + h * DK_;
        #pragma unroll
        for (int c = 0; c < 8; c++)
            op[tx + 16 * c] = o[i][c] * inv;
    }
}

// ---------------- launch ----------------
extern "C" void kernel_launch(void* const* d_in, const int* in_sizes, int n_in,
                              void* d_out, int out_size) {
    const float* query = (const float*)d_in[0];
    const float* key_t = (const float*)d_in[1];
    const float* value = (const float*)d_in[2];
    // d_in[3] = mask (always causal tril by construction; unused)
    const float* Wq = (const float*)d_in[4];
    const float* Wk = (const float*)d_in[5];
    const float* Wv = (const float*)d_in[6];
    const float* Wo = (const float*)d_in[7];
    float* out = (float*)d_out;

    float *Qb, *Kb, *Vb, *Ob;
    cudaGetSymbolAddress((void**)&Qb, g_Q);
    cudaGetSymbolAddress((void**)&Kb, g_K);
    cudaGetSymbolAddress((void**)&Vb, g_V);
    cudaGetSymbolAddress((void**)&Ob, g_O);

    // RoPE table (L*64 = 131072 entries)
    rope_table_kernel<<<512, 256>>>();

    // Projections: NT GEMMs
    gemm_nt_kernel<<<dim3(D_ / 128, M_ / 128), 256>>>(query, Wq, Qb, M_, D_, D_);
    gemm_nt_kernel<<<dim3(DKV_ / 128, M_ / 128), 256>>>(key_t, Wk, Kb, M_, DKV_, D_);
    gemm_nt_kernel<<<dim3(DKV_ / 128, M_ / 128), 256>>>(value, Wv, Vb, M_, DKV_, D_);

    // RoPE + clip on Q and K
    rope_apply_kernel<<<(M_ * H_ * 64) / 256, 256>>>(Qb, H_, D_);
    rope_apply_kernel<<<(M_ * KVH_ * 64) / 256, 256>>>(Kb, KVH_, DKV_);

    // Attention (dynamic smem > 48KB: opt in; attribute persists on the function)
    cudaFuncSetAttribute(attn_kernel, cudaFuncAttributeMaxDynamicSharedMemorySize,
                         ATTN_SMEM_BYTES);
    attn_kernel<<<dim3(L_ / 64, H_, B_), 256, ATTN_SMEM_BYTES>>>();

    // Output projection
    gemm_nt_kernel<<<dim3(D_ / 128, M_ / 128), 256>>>(Ob, Wo, out, M_, D_, D_);
}

// round 2
// speedup vs baseline: 1.5338x; 1.5338x over previous
#include <cuda_runtime.h>
#include <cuda_bf16.h>
#include <math.h>

// Problem constants
#define B_    2
#define L_    2048
#define D_    2048
#define H_    16
#define KVH_  4
#define DK_   128
#define DKV_  512            // KVH_ * DK_
#define M_    (B_ * L_)      // 4096 rows
#define CAPV  50.0f

// ---------------- scratch (static device globals; no allocation) ----------------
static __device__ float g_Q[(size_t)M_ * D_];    // 33.5 MB
static __device__ float g_K[(size_t)M_ * DKV_];  //  8.4 MB
static __device__ float g_V[(size_t)M_ * DKV_];  //  8.4 MB
static __device__ float g_O[(size_t)M_ * D_];    // 33.5 MB
static __device__ float g_cos[L_ * 64];
static __device__ float g_sin[L_ * 64];

// ---------------- RoPE table ----------------
__global__ void rope_table_kernel() {
    int idx = blockIdx.x * blockDim.x + threadIdx.x;
    if (idx >= L_ * 64) return;
    int pos = idx >> 6;
    int i   = idx & 63;
    float expnt = (float)(2 * i) / 128.0f;
    float invf  = powf(10000.0f, -expnt);
    float f     = (float)pos * invf;
    g_cos[idx] = cosf(f);
    g_sin[idx] = sinf(f);
}

// ---------------- RoPE apply + clip (in place) ----------------
__global__ void rope_apply_kernel(float* __restrict__ X, int heads, int rowstride) {
    int idx   = blockIdx.x * blockDim.x + threadIdx.x;
    int total = M_ * heads * 64;
    if (idx >= total) return;
    int i   = idx & 63;
    int t   = idx >> 6;
    int h   = t % heads;
    int row = t / heads;
    int pos = row & (L_ - 1);
    float c = g_cos[(pos << 6) + i];
    float s = g_sin[(pos << 6) + i];
    float* p = X + (size_t)row * rowstride + h * DK_ + i;
    float x1 = p[0], x2 = p[64];
    float o1 = x1 * c - x2 * s;
    float o2 = x1 * s + x2 * c;
    p[0]  = fminf(fmaxf(o1, -CAPV), CAPV);
    p[64] = fminf(fmaxf(o2, -CAPV), CAPV);
}

// ---------------- tf32 helpers ----------------
__device__ __forceinline__ float to_tf32(float x) {
    float r;
    asm("cvt.rna.tf32.f32 %0, %1;" : "=f"(r) : "f"(x));
    return r;
}

__device__ __forceinline__ void mma_tf32(float* c, const float4& a, const float2& b) {
    const unsigned* A  = reinterpret_cast<const unsigned*>(&a);
    const unsigned* Bv = reinterpret_cast<const unsigned*>(&b);
    asm volatile(
        "mma.sync.aligned.m16n8k8.row.col.f32.tf32.tf32.f32 "
        "{%0,%1,%2,%3}, {%4,%5,%6,%7}, {%8,%9}, {%0,%1,%2,%3};"
        : "+f"(c[0]), "+f"(c[1]), "+f"(c[2]), "+f"(c[3])
        : "r"(A[0]), "r"(A[1]), "r"(A[2]), "r"(A[3]), "r"(Bv[0]), "r"(Bv[1]));
}

// ---------------- tf32 tensor-core NT GEMM: C[M,N] = A[M,K] * Bw[N,K]^T ----------
// BM=BN=128, BK=32, 256 threads (8 warps, 2x4), warp tile 64x32, m16n8k8.
// Shared memory holds A/B in PERMUTED fragment layout:
//   sA4[(m_tile*4 + kstep)*32 + lane] = float4 {a0,a1,a2,a3} for that lane
//   sB2[(n_tile*4 + kstep)*32 + lane] = float2 {b0,b1}
// so mainloop fragment loads are single LDS.128 / LDS.64, conflict-free.
__global__ void __launch_bounds__(256) gemm_tf32_kernel(
    const float* __restrict__ A, const float* __restrict__ Bw,
    float* __restrict__ C, int M, int N, int K)
{
    __shared__ float4 sA4[8 * 4 * 32];    // 16 KB
    __shared__ float2 sB2[16 * 4 * 32];   // 16 KB

    const int tid    = threadIdx.x;
    const int lane   = tid & 31;
    const int wid    = tid >> 5;
    const int warp_m = wid & 1;     // 0..1 (64 rows each)
    const int warp_n = wid >> 1;    // 0..3 (32 cols each)
    const int bm     = blockIdx.y << 7;
    const int bn     = blockIdx.x << 7;

    float acc[4][4][4];
    #pragma unroll
    for (int mt = 0; mt < 4; mt++)
        #pragma unroll
        for (int nt = 0; nt < 4; nt++)
            #pragma unroll
            for (int r = 0; r < 4; r++) acc[mt][nt][r] = 0.0f;

    // global slab prefetch registers: 4 float4 each for A and B
    float4 avA[4], avB[4];
    #pragma unroll
    for (int i = 0; i < 4; i++) {
        int idx = tid + (i << 8);          // 0..1023
        int row = idx >> 3;
        int c4  = idx & 7;
        avA[i] = *(const float4*)(A  + (size_t)(bm + row) * K + (c4 << 2));
        avB[i] = *(const float4*)(Bw + (size_t)(bn + row) * K + (c4 << 2));
    }

    for (int k0 = 0; k0 < K; k0 += 32) {
        __syncthreads();
        // store slab into permuted fragment layout (with tf32 rounding)
        #pragma unroll
        for (int i = 0; i < 4; i++) {
            int idx = tid + (i << 8);
            int row = idx >> 3;
            int c4  = idx & 7;
            int ks   = c4 >> 1;
            int half = c4 & 1;
            // A: 16-row m-tiles
            {
                int mq = row >> 4;
                int rr = row & 15;
                int g  = rr & 7;
                int hi = rr >> 3;
                float* dst = (float*)&sA4[((mq * 4 + ks) << 5) + (g << 2)] + (half << 1) + hi;
                float4 v = avA[i];
                dst[0]  = to_tf32(v.x);
                dst[4]  = to_tf32(v.y);
                dst[8]  = to_tf32(v.z);
                dst[12] = to_tf32(v.w);
            }
            // B: 8-row n-tiles
            {
                int nq = row >> 3;
                int g  = row & 7;
                float* dst = (float*)&sB2[((nq * 4 + ks) << 5) + (g << 2)] + half;
                float4 v = avB[i];
                dst[0] = to_tf32(v.x);
                dst[2] = to_tf32(v.y);
                dst[4] = to_tf32(v.z);
                dst[6] = to_tf32(v.w);
            }
        }
        __syncthreads();

        // prefetch next slab while computing
        if (k0 + 32 < K) {
            #pragma unroll
            for (int i = 0; i < 4; i++) {
                int idx = tid + (i << 8);
                int row = idx >> 3;
                int c4  = idx & 7;
                avA[i] = *(const float4*)(A  + (size_t)(bm + row) * K + k0 + 32 + (c4 << 2));
                avB[i] = *(const float4*)(Bw + (size_t)(bn + row) * K + k0 + 32 + (c4 << 2));
            }
        }

        #pragma unroll
        for (int ks = 0; ks < 4; ks++) {
            float4 a[4];
            float2 b[4];
            #pragma unroll
            for (int mt = 0; mt < 4; mt++)
                a[mt] = sA4[(((warp_m * 4 + mt) * 4 + ks) << 5) + lane];
            #pragma unroll
            for (int nt = 0; nt < 4; nt++)
                b[nt] = sB2[(((warp_n * 4 + nt) * 4 + ks) << 5) + lane];
            #pragma unroll
            for (int mt = 0; mt < 4; mt++)
                #pragma unroll
                for (int nt = 0; nt < 4; nt++)
                    mma_tf32(acc[mt][nt], a[mt], b[nt]);
        }
    }

    // epilogue
    const int g   = lane >> 2;
    const int tig = lane & 3;
    #pragma unroll
    for (int mt = 0; mt < 4; mt++) {
        int r0 = bm + warp_m * 64 + mt * 16 + g;
        #pragma unroll
        for (int nt = 0; nt < 4; nt++) {
            int c = bn + warp_n * 32 + nt * 8 + (tig << 1);
            *(float2*)(&C[(size_t)r0 * N + c])       = make_float2(acc[mt][nt][0], acc[mt][nt][1]);
            *(float2*)(&C[(size_t)(r0 + 8) * N + c]) = make_float2(acc[mt][nt][2], acc[mt][nt][3]);
        }
    }
}

// ---------------- flash attention (fp32, causal) ----------------
#define AP 133   // smem pitch for 64x128 tiles
#define PP 65    // smem pitch for 64x64 P tile
#define ATTN_SMEM_FLOATS (2 * 64 * AP + 64 * PP + 3 * 64)
#define ATTN_SMEM_BYTES  (ATTN_SMEM_FLOATS * 4)

__device__ __forceinline__ void load_tile_64x128(float* dst, const float* __restrict__ src,
                                                 int rs, int tid) {
    #pragma unroll
    for (int it = 0; it < 8; it++) {
        int lin = tid + (it << 8);        // 0..2047 float4s
        int r   = lin >> 5;
        int c   = (lin & 31) << 2;
        float4 v = *(const float4*)(src + (size_t)r * rs + c);
        float* d = dst + r * AP + c;
        d[0] = v.x; d[1] = v.y; d[2] = v.z; d[3] = v.w;
    }
}

__global__ void __launch_bounds__(256) attn_kernel() {
    extern __shared__ float smbuf[];
    float* Qs  = smbuf;
    float* KVs = smbuf + 64 * AP;
    float* Ps  = smbuf + 2 * 64 * AP;
    float* smM = Ps + 64 * PP;
    float* smL = smM + 64;
    float* smF = smL + 64;

    const int tid = threadIdx.x;
    const int tx  = tid & 15;
    const int ty  = tid >> 4;
    const int qb  = blockIdx.x;
    const int h   = blockIdx.y;
    const int b   = blockIdx.z;
    const int q0  = qb << 6;
    const int kvh = h >> 2;   // REP = 4

    const float* Qg = g_Q + (size_t)(b * L_ + q0) * D_ + h * DK_;
    const float* Kg = g_K + (size_t)(b * L_) * DKV_ + kvh * DK_;
    const float* Vg = g_V + (size_t)(b * L_) * DKV_ + kvh * DK_;

    load_tile_64x128(Qs, Qg, D_, tid);
    if (tid < 64) { smM[tid] = -1e30f; smL[tid] = 0.0f; }

    float o[4][8];
    #pragma unroll
    for (int i = 0; i < 4; i++)
        #pragma unroll
        for (int c = 0; c < 8; c++) o[i][c] = 0.0f;

    const float scale = 0.08838834764831845f;  // 1/sqrt(128)
    const int nkb = qb + 1;

    for (int kb = 0; kb < nkb; kb++) {
        const int k0 = kb << 6;
        __syncthreads();
        load_tile_64x128(KVs, Kg + (size_t)k0 * DKV_, DKV_, tid);
        __syncthreads();

        // S = Q K^T
        float s[4][4];
        #pragma unroll
        for (int i = 0; i < 4; i++)
            #pragma unroll
            for (int j = 0; j < 4; j++) s[i][j] = 0.0f;

        #pragma unroll 4
        for (int d = 0; d < DK_; d++) {
            float qv[4], kv[4];
            #pragma unroll
            for (int i = 0; i < 4; i++) qv[i] = Qs[(4 * ty + i) * AP + d];
            #pragma unroll
            for (int j = 0; j < 4; j++) kv[j] = KVs[(tx + 16 * j) * AP + d];
            #pragma unroll
            for (int i = 0; i < 4; i++)
                #pragma unroll
                for (int j = 0; j < 4; j++)
                    s[i][j] += qv[i] * kv[j];
        }

        #pragma unroll
        for (int i = 0; i < 4; i++) {
            int r = 4 * ty + i;
            #pragma unroll
            for (int j = 0; j < 4; j++) {
                int c = tx + 16 * j;
                float val = s[i][j] * scale;
                if (k0 + c > q0 + r) val = -1e30f;   // causal mask
                Ps[r * PP + c] = val;
            }
        }
        __syncthreads();

        // online softmax, one thread per row
        if (tid < 64) {
            int r = tid;
            float m0 = smM[r];
            float mx = m0;
            #pragma unroll 4
            for (int c = 0; c < 64; c++) mx = fmaxf(mx, Ps[r * PP + c]);
            float fac = __expf(m0 - mx);
            float l = smL[r] * fac;
            #pragma unroll 4
            for (int c = 0; c < 64; c++) {
                float p = __expf(Ps[r * PP + c] - mx);
                Ps[r * PP + c] = p;
                l += p;
            }
            smM[r] = mx; smL[r] = l; smF[r] = fac;
        }
        __syncthreads();

        // rescale O; load V over the K buffer
        float f[4];
        #pragma unroll
        for (int i = 0; i < 4; i++) f[i] = smF[4 * ty + i];
        #pragma unroll
        for (int i = 0; i < 4; i++)
            #pragma unroll
            for (int c = 0; c < 8; c++) o[i][c] *= f[i];

        load_tile_64x128(KVs, Vg + (size_t)k0 * DKV_, DKV_, tid);
        __syncthreads();

        // O += P V
        #pragma unroll 2
        for (int kk = 0; kk < 64; kk++) {
            float p[4], v[8];
            #pragma unroll
            for (int i = 0; i < 4; i++) p[i] = Ps[(4 * ty + i) * PP + kk];
            #pragma unroll
            for (int c = 0; c < 8; c++) v[c] = KVs[kk * AP + tx + 16 * c];
            #pragma unroll
            for (int i = 0; i < 4; i++)
                #pragma unroll
                for (int c = 0; c < 8; c++)
                    o[i][c] += p[i] * v[c];
        }
    }

    // epilogue: normalize and write
    #pragma unroll
    for (int i = 0; i < 4; i++) {
        int r = 4 * ty + i;
        float inv = 1.0f / smL[r];
        float* op = g_O + (size_t)(b * L_ + q0 + r) * D_ + h * DK_;
        #pragma unroll
        for (int c = 0; c < 8; c++)
            op[tx + 16 * c] = o[i][c] * inv;
    }
}

// ---------------- launch ----------------
extern "C" void kernel_launch(void* const* d_in, const int* in_sizes, int n_in,
                              void* d_out, int out_size) {
    const float* query = (const float*)d_in[0];
    const float* key_t = (const float*)d_in[1];
    const float* value = (const float*)d_in[2];
    // d_in[3] = mask (always causal tril by construction; unused)
    const float* Wq = (const float*)d_in[4];
    const float* Wk = (const float*)d_in[5];
    const float* Wv = (const float*)d_in[6];
    const float* Wo = (const float*)d_in[7];
    float* out = (float*)d_out;

    float *Qb, *Kb, *Vb, *Ob;
    cudaGetSymbolAddress((void**)&Qb, g_Q);
    cudaGetSymbolAddress((void**)&Kb, g_K);
    cudaGetSymbolAddress((void**)&Vb, g_V);
    cudaGetSymbolAddress((void**)&Ob, g_O);

    // RoPE table
    rope_table_kernel<<<512, 256>>>();

    // Projections: tf32 tensor-core NT GEMMs
    gemm_tf32_kernel<<<dim3(D_ / 128, M_ / 128), 256>>>(query, Wq, Qb, M_, D_, D_);
    gemm_tf32_kernel<<<dim3(DKV_ / 128, M_ / 128), 256>>>(key_t, Wk, Kb, M_, DKV_, D_);
    gemm_tf32_kernel<<<dim3(DKV_ / 128, M_ / 128), 256>>>(value, Wv, Vb, M_, DKV_, D_);

    // RoPE + clip on Q and K
    rope_apply_kernel<<<(M_ * H_ * 64) / 256, 256>>>(Qb, H_, D_);
    rope_apply_kernel<<<(M_ * KVH_ * 64) / 256, 256>>>(Kb, KVH_, DKV_);

    // Attention
    cudaFuncSetAttribute(attn_kernel, cudaFuncAttributeMaxDynamicSharedMemorySize,
                         ATTN_SMEM_BYTES);
    attn_kernel<<<dim3(L_ / 64, H_, B_), 256, ATTN_SMEM_BYTES>>>();

    // Output projection
    gemm_tf32_kernel<<<dim3(D_ / 128, M_ / 128), 256>>>(Ob, Wo, out, M_, D_, D_);
}